// round 6
// baseline (speedup 1.0000x reference)
#include <cuda_runtime.h>
#include <math.h>

#define NN 8192
#define FF 64
#define DI 32
#define B  4096

// ---------------- scratch (device globals; no allocation allowed) ----------------
__device__ float    g_h[NN*FF];
__device__ float    g_s[NN], g_t[NN];
__device__ float    g_e1[NN], g_e2[NN];     // e^{s_k}, e^{0.2 s_k}
__device__ float    g_w1[NN], g_w2[NN];     // e^{t_j}/denom, e^{0.2 t_j}/denom
__device__ int      g_tbin[NN], g_obin[NN];
__device__ int      g_sStart[B+1], g_tStart[B+1];
__device__ int      g_sOrder[NN], g_tOrder[NN];
__device__ float    g_Suf1[B], g_Pre2[B];   // strict suffix/prefix over s-bins
__device__ float    g_B1[B*FF], g_B2[B*FF]; // per-t-bin vector sums -> scanned in place
__device__ unsigned g_pmm[256*4];           // per-gemm-block {smin,smax,tmin,tmax} keys
__device__ float    g_range[4];             // {smn, sinv, tmn, tinv}

__device__ __forceinline__ float wscan(float v, int lane) {
#pragma unroll
    for (int o = 1; o < 32; o <<= 1) {
        float n = __shfl_up_sync(0xffffffffu, v, o);
        if (lane >= o) v += n;
    }
    return v;
}
__device__ __forceinline__ int iwscan(int v, int lane) {
#pragma unroll
    for (int o = 1; o < 32; o <<= 1) {
        int n = __shfl_up_sync(0xffffffffu, v, o);
        if (lane >= o) v += n;
    }
    return v;
}
__device__ __forceinline__ unsigned toKey(float f) {
    unsigned u = __float_as_uint(f);
    return u ^ ((u >> 31) ? 0xFFFFFFFFu : 0x80000000u);
}
__device__ __forceinline__ float fromKey(unsigned u) {
    return __uint_as_float(u ^ ((u >> 31) ? 0x80000000u : 0xFFFFFFFFu));
}
__device__ __forceinline__ int binof(float v, float mn, float inv) {
    int b = (int)((v - mn) * inv);
    return b < 0 ? 0 : (b > B - 1 ? B - 1 : b);
}

// ---------------- K1: fused h = x@W + s,t + minmax partials + zeroing -----------
__global__ void k_gemm(const float* __restrict__ x, const float* __restrict__ W,
                       const float* __restrict__ intent, const float* __restrict__ a) {
    __shared__ float Ws[64*64];
    __shared__ float xs[32*64];
    __shared__ float as[192];
    __shared__ float red_s[32][2];
    __shared__ float red_t[32][2];
    int tid = threadIdx.x;
    int bid = blockIdx.x;
    int row0 = bid * 32;
    // zero accumulation arrays (grid-stride over 256 blocks)
    for (int i = bid*256 + tid; i < B*FF; i += 256*256) { g_B1[i] = 0.f; g_B2[i] = 0.f; }
    for (int i = tid; i < 64*64; i += 256) Ws[i] = W[i];
    for (int i = tid; i < 32*64; i += 256) xs[i] = x[row0*64 + i];
    if (tid < 192) as[tid] = a[tid];
    __syncthreads();
    int f = tid & 63, rq = tid >> 6, lane = tid & 31;
    float acc[8];
#pragma unroll
    for (int m = 0; m < 8; m++) acc[m] = 0.f;
    for (int k = 0; k < 64; k++) {
        float w = Ws[k*64 + f];
#pragma unroll
        for (int m = 0; m < 8; m++) acc[m] += xs[(rq + 4*m)*64 + k] * w;
    }
#pragma unroll
    for (int m = 0; m < 8; m++) g_h[(row0 + rq + 4*m)*64 + f] = acc[m];
    float asrc = as[f], adst = as[64 + f];
    float ps[8], pt[8];
#pragma unroll
    for (int m = 0; m < 8; m++) { ps[m] = acc[m]*asrc; pt[m] = acc[m]*adst; }
#pragma unroll
    for (int o = 16; o; o >>= 1) {
#pragma unroll
        for (int m = 0; m < 8; m++) {
            ps[m] += __shfl_down_sync(0xffffffffu, ps[m], o);
            pt[m] += __shfl_down_sync(0xffffffffu, pt[m], o);
        }
    }
    int wh = f >> 5;
    if (lane == 0) {
#pragma unroll
        for (int m = 0; m < 8; m++) {
            red_s[rq + 4*m][wh] = ps[m];
            red_t[rq + 4*m][wh] = pt[m];
        }
    }
    __syncthreads();
    if (tid < 32) {
        int r = tid;
        float s = red_s[r][0] + red_s[r][1];
        float t = red_t[r][0] + red_t[r][1];
        const float* iv = &intent[(row0 + r)*32];
#pragma unroll
        for (int d = 0; d < 32; d++) {
            float v = iv[d];
            s += v * as[128 + d];
            t += v * as[160 + d];
        }
        g_s[row0 + r] = s;
        g_t[row0 + r] = t;
        unsigned skn = toKey(s), skx = skn, tkn = toKey(t), tkx = tkn;
#pragma unroll
        for (int o = 16; o; o >>= 1) {
            skn = min(skn, __shfl_xor_sync(0xffffffffu, skn, o));
            skx = max(skx, __shfl_xor_sync(0xffffffffu, skx, o));
            tkn = min(tkn, __shfl_xor_sync(0xffffffffu, tkn, o));
            tkx = max(tkx, __shfl_xor_sync(0xffffffffu, tkx, o));
        }
        if (tid == 0) {
            g_pmm[bid*4 + 0] = skn; g_pmm[bid*4 + 1] = skx;
            g_pmm[bid*4 + 2] = tkn; g_pmm[bid*4 + 3] = tkx;
        }
    }
}

// ---------------- K2: hub (1 block, 64KB dyn smem) ------------------------------
// ranges -> bins/exps/counts (smem atomics) -> scans -> bucket placement
__global__ __launch_bounds__(1024, 1) void k_hub() {
    extern __shared__ int dyn[];
    int*   cntS = dyn;             // B
    int*   cntT = dyn + B;         // B
    float* e1s  = (float*)(dyn + 2*B); // B
    float* e2s  = (float*)(dyn + 3*B); // B
    __shared__ unsigned shA[32], shB[32], shC[32], shD[32];
    __shared__ float rng[4];
    __shared__ int   wqi[32];
    __shared__ float wqf[32];
    __shared__ float ftot;
    int tid = threadIdx.x, lane = tid & 31, wid = tid >> 5;

    // ---- range reduction (all 1024 threads; entries duplicated x4) ----
    {
        int e = tid & 255;
        unsigned smn = g_pmm[e*4+0], smx = g_pmm[e*4+1];
        unsigned tmn = g_pmm[e*4+2], tmx = g_pmm[e*4+3];
#pragma unroll
        for (int o = 16; o; o >>= 1) {
            smn = min(smn, __shfl_xor_sync(0xffffffffu, smn, o));
            smx = max(smx, __shfl_xor_sync(0xffffffffu, smx, o));
            tmn = min(tmn, __shfl_xor_sync(0xffffffffu, tmn, o));
            tmx = max(tmx, __shfl_xor_sync(0xffffffffu, tmx, o));
        }
        if (lane == 0) { shA[wid] = smn; shB[wid] = smx; shC[wid] = tmn; shD[wid] = tmx; }
    }
    // zero smem count/sum arrays while waiting
    for (int i = tid; i < B; i += 1024) { cntS[i] = 0; cntT[i] = 0; e1s[i] = 0.f; e2s[i] = 0.f; }
    __syncthreads();
    if (tid == 0) {
        unsigned a0 = shA[0], b0 = shB[0], c0 = shC[0], d0 = shD[0];
#pragma unroll
        for (int i = 1; i < 32; i++) {
            a0 = min(a0, shA[i]); b0 = max(b0, shB[i]);
            c0 = min(c0, shC[i]); d0 = max(d0, shD[i]);
        }
        float smn = fromKey(a0);
        float sinv = (float)B / fmaxf(fromKey(b0) - smn, 1e-20f);
        float tmn = fromKey(c0);
        float tinv = (float)B / fmaxf(fromKey(d0) - tmn, 1e-20f);
        rng[0] = smn; rng[1] = sinv; rng[2] = tmn; rng[3] = tinv;
        g_range[0] = smn; g_range[1] = sinv; g_range[2] = tmn; g_range[3] = tinv;
    }
    __syncthreads();
    float smn = rng[0], sinv = rng[1], tmn = rng[2], tinv = rng[3];

    // ---- bins, exps, counts, E sums ----
    int r_sb[8], r_tb[8];
#pragma unroll
    for (int e = 0; e < 8; e++) {
        int k = tid * 8 + e;
        float s = g_s[k], t = g_t[k];
        float e1 = expf(s), e2 = expf(0.2f * s);
        g_e1[k] = e1; g_e2[k] = e2;
        int sb = binof(s, smn, sinv);
        int tb = binof(t, tmn, tinv);
        r_sb[e] = sb; r_tb[e] = tb;
        g_tbin[k] = tb;
        g_obin[k] = binof(-s, tmn, tinv);
        atomicAdd(&cntS[sb], 1);
        atomicAdd(&cntT[tb], 1);
        atomicAdd(&e1s[sb], e1);
        atomicAdd(&e2s[sb], e2);
    }
    __syncthreads();

    int b4 = tid * 4;
    // ---- s counts -> sStart (cursor left in cntS) ----
    {
        int c0 = cntS[b4], c1 = cntS[b4+1], c2 = cntS[b4+2], c3 = cntS[b4+3];
        int ls = c0 + c1 + c2 + c3;
        int inc = iwscan(ls, lane);
        if (lane == 31) wqi[wid] = inc;
        __syncthreads();
        if (wid == 0) { int v = wqi[lane]; int w = iwscan(v, lane); wqi[lane] = w - v; }
        __syncthreads();
        int excl = inc - ls + wqi[wid];
        int s0 = excl, s1 = s0 + c0, s2 = s1 + c1, s3 = s2 + c2;
        g_sStart[b4] = s0; g_sStart[b4+1] = s1; g_sStart[b4+2] = s2; g_sStart[b4+3] = s3;
        __syncthreads();
        cntS[b4] = s0; cntS[b4+1] = s1; cntS[b4+2] = s2; cntS[b4+3] = s3;
        if (tid == 1023) g_sStart[B] = s3 + c3;
    }
    // ---- t counts -> tStart (cursor left in cntT) ----
    {
        int c0 = cntT[b4], c1 = cntT[b4+1], c2 = cntT[b4+2], c3 = cntT[b4+3];
        int ls = c0 + c1 + c2 + c3;
        int inc = iwscan(ls, lane);
        if (lane == 31) wqi[wid] = inc;
        __syncthreads();
        if (wid == 0) { int v = wqi[lane]; int w = iwscan(v, lane); wqi[lane] = w - v; }
        __syncthreads();
        int excl = inc - ls + wqi[wid];
        int s0 = excl, s1 = s0 + c0, s2 = s1 + c1, s3 = s2 + c2;
        g_tStart[b4] = s0; g_tStart[b4+1] = s1; g_tStart[b4+2] = s2; g_tStart[b4+3] = s3;
        __syncthreads();
        cntT[b4] = s0; cntT[b4+1] = s1; cntT[b4+2] = s2; cntT[b4+3] = s3;
        if (tid == 1023) g_tStart[B] = s3 + c3;
    }
    __syncthreads();
    // ---- place s and t orders ----
#pragma unroll
    for (int e = 0; e < 8; e++) {
        int k = tid * 8 + e;
        int ps = atomicAdd(&cntS[r_sb[e]], 1);
        g_sOrder[ps] = k;
        int pt = atomicAdd(&cntT[r_tb[e]], 1);
        g_tOrder[pt] = k;
    }
    // ---- E1 strict suffix, E2 strict prefix over s-bins ----
    {
        float v0 = e1s[b4], v1 = e1s[b4+1], v2 = e1s[b4+2], v3 = e1s[b4+3];
        float ls = v0 + v1 + v2 + v3;
        float inc = wscan(ls, lane);
        if (lane == 31) wqf[wid] = inc;
        __syncthreads();
        if (wid == 0) { float v = wqf[lane]; float w = wscan(v, lane); wqf[lane] = w - v; }
        __syncthreads();
        float excl = inc - ls + wqf[wid];
        if (tid == 1023) ftot = excl + ls;
        __syncthreads();
        float total = ftot;
        float run = excl;
        run += v0; g_Suf1[b4]   = total - run;
        run += v1; g_Suf1[b4+1] = total - run;
        run += v2; g_Suf1[b4+2] = total - run;
        run += v3; g_Suf1[b4+3] = total - run;
    }
    __syncthreads();
    {
        float v0 = e2s[b4], v1 = e2s[b4+1], v2 = e2s[b4+2], v3 = e2s[b4+3];
        float ls = v0 + v1 + v2 + v3;
        float inc = wscan(ls, lane);
        if (lane == 31) wqf[wid] = inc;
        __syncthreads();
        if (wid == 0) { float v = wqf[lane]; float w = wscan(v, lane); wqf[lane] = w - v; }
        __syncthreads();
        float excl = inc - ls + wqf[wid];
        float run = excl;
        g_Pre2[b4]   = run; run += v0;
        g_Pre2[b4+1] = run; run += v1;
        g_Pre2[b4+2] = run; run += v2;
        g_Pre2[b4+3] = run;
    }
}

// ---------------- K3: weights (exact denom) + bin-vector accumulation -----------
__global__ void k_wacc() {
    int tid = threadIdx.x, lane = tid & 31;
    float smn = g_range[0], sinv = g_range[1];

    int j = blockIdx.x * 8 + (tid >> 5);
    float tj = g_t[j];
    float u = -tj;
    int b = binof(u, smn, sinv);
    float a1 = 0.f, a2 = 0.f;
    int st = g_sStart[b], en = g_sStart[b+1];
    for (int m = st + lane; m < en; m += 32) {
        int k = g_sOrder[m];
        float sk = g_s[k];
        if (sk > u) a1 += g_e1[k]; else a2 += g_e2[k];
    }
#pragma unroll
    for (int o = 16; o; o >>= 1) {
        a1 += __shfl_xor_sync(0xffffffffu, a1, o);
        a2 += __shfl_xor_sync(0xffffffffu, a2, o);
    }
    float et  = expf(tj);
    float et2 = expf(0.2f * tj);
    float denom = et * (g_Suf1[b] + a1) + et2 * (g_Pre2[b] + a2);
    float w1 = et / denom, w2 = et2 / denom;
    if (lane == 0) { g_w1[j] = w1; g_w2[j] = w2; }
    int tb = g_tbin[j];
    float h0 = g_h[j*64 + lane], h1 = g_h[j*64 + 32 + lane];
    atomicAdd(&g_B1[tb*64 + lane],      w1 * h0);
    atomicAdd(&g_B1[tb*64 + 32 + lane], w1 * h1);
    atomicAdd(&g_B2[tb*64 + lane],      w2 * h0);
    atomicAdd(&g_B2[tb*64 + 32 + lane], w2 * h1);
}

// ---------------- K4: per-f strict suffix/prefix scans over t-bins (in place) ---
__global__ __launch_bounds__(1024, 1) void k_gscan() {
    __shared__ float wqf[32];
    __shared__ float ftot;
    int f = blockIdx.x;
    int tid = threadIdx.x, lane = tid & 31, wid = tid >> 5;
    int b4 = tid * 4;
    float v1[4], v2[4];
#pragma unroll
    for (int i = 0; i < 4; i++) {
        v1[i] = g_B1[(b4 + i)*64 + f];
        v2[i] = g_B2[(b4 + i)*64 + f];
    }
    float l1 = v1[0]+v1[1]+v1[2]+v1[3];
    float l2 = v2[0]+v2[1]+v2[2]+v2[3];
    float inc1 = wscan(l1, lane);
    if (lane == 31) wqf[wid] = inc1;
    __syncthreads();
    if (wid == 0) { float v = wqf[lane]; float w = wscan(v, lane); wqf[lane] = w - v; }
    __syncthreads();
    float excl1 = inc1 - l1 + wqf[wid];
    if (tid == 1023) ftot = excl1 + l1;
    __syncthreads();
    float total1 = ftot;
    __syncthreads();
    float inc2 = wscan(l2, lane);
    if (lane == 31) wqf[wid] = inc2;
    __syncthreads();
    if (wid == 0) { float v = wqf[lane]; float w = wscan(v, lane); wqf[lane] = w - v; }
    __syncthreads();
    float excl2 = inc2 - l2 + wqf[wid];

    float run = excl1;
#pragma unroll
    for (int i = 0; i < 4; i++) { run += v1[i]; g_B1[(b4 + i)*64 + f] = total1 - run; }
    float run2 = excl2;
#pragma unroll
    for (int i = 0; i < 4; i++) { g_B2[(b4 + i)*64 + f] = run2; run2 += v2[i]; }
}

// ---------------- K5: coalesced epilogue with exact boundary bucket -------------
__global__ void k_out(float* __restrict__ out) {
    int idx = blockIdx.x * 256 + threadIdx.x;
    int i = idx >> 6, f = idx & 63;
    int b = g_obin[i];
    float ui = -g_s[i];
    float e1 = g_e1[i], e2 = g_e2[i];
    float acc = e1 * g_B1[b*64 + f] + e2 * g_B2[b*64 + f];
    int st = g_tStart[b], en = g_tStart[b+1];
    for (int m = st; m < en; m++) {
        int j = g_tOrder[m];
        float tj = g_t[j];
        float hv = g_h[j*64 + f];
        acc += (tj > ui) ? e1 * g_w1[j] * hv : e2 * g_w2[j] * hv;
    }
    out[idx] = acc > 0.f ? acc : expm1f(acc);
}

// ---------------- launch ----------------
extern "C" void kernel_launch(void* const* d_in, const int* in_sizes, int n_in,
                              void* d_out, int out_size) {
    const float* x      = (const float*)d_in[0];
    // d_in[1] = adj (all-ones bool mask; no effect on the math)
    const float* intent = (const float*)d_in[2];
    const float* W      = (const float*)d_in[3];
    const float* a      = (const float*)d_in[4];
    float* out = (float*)d_out;

    static int smem_set = 0;
    if (!smem_set) {
        cudaFuncSetAttribute(k_hub, cudaFuncAttributeMaxDynamicSharedMemorySize, 4*B*(int)sizeof(int));
        smem_set = 1;
    }

    k_gemm <<<256,  256>>>(x, W, intent, a);
    k_hub  <<<1,   1024, 4*B*sizeof(int)>>>();
    k_wacc <<<NN/8, 256>>>();
    k_gscan<<<FF,  1024>>>();
    k_out  <<<(NN*FF)/256, 256>>>(out);
}

// round 7
// speedup vs baseline: 1.3695x; 1.3695x over previous
#include <cuda_runtime.h>
#include <math.h>

#define NN 8192
#define FF 64
#define DI 32
#define B  1024

// ---------------- scratch (device globals; no allocation allowed) ----------------
__device__ float    g_h[NN*FF];
__device__ float    g_s[NN], g_t[NN];
__device__ float    g_e1[NN], g_e2[NN];     // e^{s_k}, e^{0.2 s_k}
__device__ float    g_w1[NN], g_w2[NN];     // e^{t_j}/denom, e^{0.2 t_j}/denom
__device__ int      g_sbin[NN], g_tbin[NN], g_obin[NN];
__device__ int      g_sCnt[B], g_tCnt[B];
__device__ int      g_sStart[B+1], g_tStart[B+1];
__device__ int      g_sOrder[NN], g_tOrder[NN];
__device__ float    g_E1[B], g_E2[B];       // per-s-bin sums of e1,e2
__device__ float    g_Suf1[B], g_Pre2[B];   // strict suffix/prefix over s-bins
__device__ float    g_B1[B*FF], g_B2[B*FF]; // per-t-bin vector sums -> scanned in place
__device__ unsigned g_pmm[256*4];           // per-gemm-block {smin,smax,tmin,tmax} keys
__device__ float    g_range[4];             // {smn, sinv, tmn, tinv}

__device__ __forceinline__ float wscan(float v, int lane) {
#pragma unroll
    for (int o = 1; o < 32; o <<= 1) {
        float n = __shfl_up_sync(0xffffffffu, v, o);
        if (lane >= o) v += n;
    }
    return v;
}
__device__ __forceinline__ int iwscan(int v, int lane) {
#pragma unroll
    for (int o = 1; o < 32; o <<= 1) {
        int n = __shfl_up_sync(0xffffffffu, v, o);
        if (lane >= o) v += n;
    }
    return v;
}
__device__ __forceinline__ unsigned toKey(float f) {
    unsigned u = __float_as_uint(f);
    return u ^ ((u >> 31) ? 0xFFFFFFFFu : 0x80000000u);
}
__device__ __forceinline__ float fromKey(unsigned u) {
    return __uint_as_float(u ^ ((u >> 31) ? 0x80000000u : 0xFFFFFFFFu));
}
__device__ __forceinline__ int binof(float v, float mn, float inv) {
    int b = (int)((v - mn) * inv);
    return b < 0 ? 0 : (b > B - 1 ? B - 1 : b);
}

// ---------------- K1: fused h = x@W + s,t + minmax partials + zeroing -----------
__global__ void k_gemm(const float* __restrict__ x, const float* __restrict__ W,
                       const float* __restrict__ intent, const float* __restrict__ a) {
    __shared__ float Ws[64*64];
    __shared__ float xs[32*64];
    __shared__ float as[192];
    __shared__ float red_s[32][2];
    __shared__ float red_t[32][2];
    int tid = threadIdx.x;
    int bid = blockIdx.x;
    int row0 = bid * 32;
    // zero accumulation arrays (65536 threads cover everything)
    {
        int i = bid*256 + tid;
        g_B1[i] = 0.f; g_B2[i] = 0.f;           // B*FF == 65536
        if (i < B) { g_sCnt[i] = 0; g_tCnt[i] = 0; g_E1[i] = 0.f; g_E2[i] = 0.f; }
    }
    for (int i = tid; i < 64*64; i += 256) Ws[i] = W[i];
    for (int i = tid; i < 32*64; i += 256) xs[i] = x[row0*64 + i];
    if (tid < 192) as[tid] = a[tid];
    __syncthreads();
    int f = tid & 63, rq = tid >> 6, lane = tid & 31;
    float acc[8];
#pragma unroll
    for (int m = 0; m < 8; m++) acc[m] = 0.f;
    for (int k = 0; k < 64; k++) {
        float w = Ws[k*64 + f];
#pragma unroll
        for (int m = 0; m < 8; m++) acc[m] += xs[(rq + 4*m)*64 + k] * w;
    }
#pragma unroll
    for (int m = 0; m < 8; m++) g_h[(row0 + rq + 4*m)*64 + f] = acc[m];
    float asrc = as[f], adst = as[64 + f];
    float ps[8], pt[8];
#pragma unroll
    for (int m = 0; m < 8; m++) { ps[m] = acc[m]*asrc; pt[m] = acc[m]*adst; }
#pragma unroll
    for (int o = 16; o; o >>= 1) {
#pragma unroll
        for (int m = 0; m < 8; m++) {
            ps[m] += __shfl_down_sync(0xffffffffu, ps[m], o);
            pt[m] += __shfl_down_sync(0xffffffffu, pt[m], o);
        }
    }
    int wh = f >> 5;
    if (lane == 0) {
#pragma unroll
        for (int m = 0; m < 8; m++) {
            red_s[rq + 4*m][wh] = ps[m];
            red_t[rq + 4*m][wh] = pt[m];
        }
    }
    __syncthreads();
    if (tid < 32) {
        int r = tid;
        float s = red_s[r][0] + red_s[r][1];
        float t = red_t[r][0] + red_t[r][1];
        const float* iv = &intent[(row0 + r)*32];
#pragma unroll
        for (int d = 0; d < 32; d++) {
            float v = iv[d];
            s += v * as[128 + d];
            t += v * as[160 + d];
        }
        g_s[row0 + r] = s;
        g_t[row0 + r] = t;
        unsigned skn = toKey(s), skx = skn, tkn = toKey(t), tkx = tkn;
#pragma unroll
        for (int o = 16; o; o >>= 1) {
            skn = min(skn, __shfl_xor_sync(0xffffffffu, skn, o));
            skx = max(skx, __shfl_xor_sync(0xffffffffu, skx, o));
            tkn = min(tkn, __shfl_xor_sync(0xffffffffu, tkn, o));
            tkx = max(tkx, __shfl_xor_sync(0xffffffffu, tkx, o));
        }
        if (tid == 0) {
            g_pmm[bid*4 + 0] = skn; g_pmm[bid*4 + 1] = skx;
            g_pmm[bid*4 + 2] = tkn; g_pmm[bid*4 + 3] = tkx;
        }
    }
}

// ---------------- K2: bins, exps, counts, E sums (32 blocks) --------------------
__global__ void k_count() {
    __shared__ unsigned shm[4][8];
    int tid = threadIdx.x, lane = tid & 31, wid = tid >> 5;
    // full range reduction (256 entries, bit-identical in every block)
    unsigned smn = g_pmm[tid*4 + 0], smx = g_pmm[tid*4 + 1];
    unsigned tmn = g_pmm[tid*4 + 2], tmx = g_pmm[tid*4 + 3];
#pragma unroll
    for (int o = 16; o; o >>= 1) {
        smn = min(smn, __shfl_xor_sync(0xffffffffu, smn, o));
        smx = max(smx, __shfl_xor_sync(0xffffffffu, smx, o));
        tmn = min(tmn, __shfl_xor_sync(0xffffffffu, tmn, o));
        tmx = max(tmx, __shfl_xor_sync(0xffffffffu, tmx, o));
    }
    if (lane == 0) { shm[0][wid] = smn; shm[1][wid] = smx; shm[2][wid] = tmn; shm[3][wid] = tmx; }
    __syncthreads();
    unsigned a0 = shm[0][0], b0 = shm[1][0], c0 = shm[2][0], d0 = shm[3][0];
#pragma unroll
    for (int i = 1; i < 8; i++) {
        a0 = min(a0, shm[0][i]); b0 = max(b0, shm[1][i]);
        c0 = min(c0, shm[2][i]); d0 = max(d0, shm[3][i]);
    }
    float fsmn = fromKey(a0);
    float sinv = (float)B / fmaxf(fromKey(b0) - fsmn, 1e-20f);
    float ftmn = fromKey(c0);
    float tinv = (float)B / fmaxf(fromKey(d0) - ftmn, 1e-20f);
    if (blockIdx.x == 0 && tid == 0) {
        g_range[0] = fsmn; g_range[1] = sinv; g_range[2] = ftmn; g_range[3] = tinv;
    }

    int k = blockIdx.x * 256 + tid;
    float s = g_s[k], t = g_t[k];
    float e1 = expf(s), e2 = expf(0.2f * s);
    g_e1[k] = e1; g_e2[k] = e2;
    int sb = binof(s, fsmn, sinv); g_sbin[k] = sb;
    atomicAdd(&g_sCnt[sb], 1);
    atomicAdd(&g_E1[sb], e1);
    atomicAdd(&g_E2[sb], e2);
    int tb = binof(t, ftmn, tinv); g_tbin[k] = tb;
    atomicAdd(&g_tCnt[tb], 1);
    g_obin[k] = binof(-s, ftmn, tinv);
}

// ---------------- K3: hub (1 block): bin scans + bucket-list placement ----------
__global__ __launch_bounds__(1024, 1) void k_hub() {
    __shared__ int   curS[B], curT[B];
    __shared__ int   wqi[32];
    __shared__ float wqf[32];
    __shared__ float ftot;
    int tid = threadIdx.x, lane = tid & 31, wid = tid >> 5;

    // ---- s counts -> sStart ----
    int cs = g_sCnt[tid];
    int ct = g_tCnt[tid];
    {
        int inc = iwscan(cs, lane);
        if (lane == 31) wqi[wid] = inc;
        __syncthreads();
        if (wid == 0) { int v = wqi[lane]; int w = iwscan(v, lane); wqi[lane] = w - v; }
        __syncthreads();
        int excl = inc - cs + wqi[wid];
        g_sStart[tid] = excl; curS[tid] = excl;
        if (tid == 1023) g_sStart[B] = excl + cs;
    }
    __syncthreads();
    // ---- t counts -> tStart ----
    {
        int inc = iwscan(ct, lane);
        if (lane == 31) wqi[wid] = inc;
        __syncthreads();
        if (wid == 0) { int v = wqi[lane]; int w = iwscan(v, lane); wqi[lane] = w - v; }
        __syncthreads();
        int excl = inc - ct + wqi[wid];
        g_tStart[tid] = excl; curT[tid] = excl;
        if (tid == 1023) g_tStart[B] = excl + ct;
    }
    __syncthreads();
    // ---- place s and t bucket lists ----
#pragma unroll
    for (int e = 0; e < 8; e++) {
        int k = tid * 8 + e;
        int ps = atomicAdd(&curS[g_sbin[k]], 1);
        g_sOrder[ps] = k;
        int pt = atomicAdd(&curT[g_tbin[k]], 1);
        g_tOrder[pt] = k;
    }
    // ---- E1 strict suffix, E2 strict prefix over s-bins ----
    {
        float v = g_E1[tid];
        float inc = wscan(v, lane);
        if (lane == 31) wqf[wid] = inc;
        __syncthreads();
        if (wid == 0) { float q = wqf[lane]; float w = wscan(q, lane); wqf[lane] = w - q; }
        __syncthreads();
        float incl = inc + wqf[wid];
        if (tid == 1023) ftot = incl;
        __syncthreads();
        g_Suf1[tid] = ftot - incl;   // strict suffix: bins > tid
    }
    __syncthreads();
    {
        float v = g_E2[tid];
        float inc = wscan(v, lane);
        if (lane == 31) wqf[wid] = inc;
        __syncthreads();
        if (wid == 0) { float q = wqf[lane]; float w = wscan(q, lane); wqf[lane] = w - q; }
        __syncthreads();
        float incl = inc + wqf[wid];
        g_Pre2[tid] = incl - v;      // strict prefix: bins < tid
    }
}

// ---------------- K4: weights (exact denom) + bin-vector accumulation -----------
__global__ void k_wacc() {
    int tid = threadIdx.x, lane = tid & 31;
    float smn = g_range[0], sinv = g_range[1];

    int j = blockIdx.x * 8 + (tid >> 5);
    float tj = g_t[j];
    float u = -tj;
    int b = binof(u, smn, sinv);
    float a1 = 0.f, a2 = 0.f;
    int st = g_sStart[b], en = g_sStart[b+1];
    for (int m = st + lane; m < en; m += 32) {
        int k = g_sOrder[m];
        float sk = g_s[k];
        if (sk > u) a1 += g_e1[k]; else a2 += g_e2[k];
    }
#pragma unroll
    for (int o = 16; o; o >>= 1) {
        a1 += __shfl_xor_sync(0xffffffffu, a1, o);
        a2 += __shfl_xor_sync(0xffffffffu, a2, o);
    }
    float et  = expf(tj);
    float et2 = expf(0.2f * tj);
    float denom = et * (g_Suf1[b] + a1) + et2 * (g_Pre2[b] + a2);
    float w1 = et / denom, w2 = et2 / denom;
    if (lane == 0) { g_w1[j] = w1; g_w2[j] = w2; }
    int tb = g_tbin[j];
    float h0 = g_h[j*64 + lane], h1 = g_h[j*64 + 32 + lane];
    atomicAdd(&g_B1[tb*64 + lane],      w1 * h0);
    atomicAdd(&g_B1[tb*64 + 32 + lane], w1 * h1);
    atomicAdd(&g_B2[tb*64 + lane],      w2 * h0);
    atomicAdd(&g_B2[tb*64 + 32 + lane], w2 * h1);
}

// ---------------- K5: per-f strict suffix/prefix scans over t-bins (in place) ---
__global__ __launch_bounds__(1024, 1) void k_gscan() {
    __shared__ float wqf[32];
    __shared__ float ftot;
    int f = blockIdx.x;
    int tid = threadIdx.x, lane = tid & 31, wid = tid >> 5;
    float v1 = g_B1[tid*64 + f];
    float v2 = g_B2[tid*64 + f];
    {
        float inc = wscan(v1, lane);
        if (lane == 31) wqf[wid] = inc;
        __syncthreads();
        if (wid == 0) { float q = wqf[lane]; float w = wscan(q, lane); wqf[lane] = w - q; }
        __syncthreads();
        float incl = inc + wqf[wid];
        if (tid == 1023) ftot = incl;
        __syncthreads();
        g_B1[tid*64 + f] = ftot - incl;   // strict suffix over t-bins
    }
    __syncthreads();
    {
        float inc = wscan(v2, lane);
        if (lane == 31) wqf[wid] = inc;
        __syncthreads();
        if (wid == 0) { float q = wqf[lane]; float w = wscan(q, lane); wqf[lane] = w - q; }
        __syncthreads();
        float incl = inc + wqf[wid];
        g_B2[tid*64 + f] = incl - v2;     // strict prefix over t-bins
    }
}

// ---------------- K6: coalesced epilogue with exact boundary bucket -------------
__global__ void k_out(float* __restrict__ out) {
    int idx = blockIdx.x * 256 + threadIdx.x;
    int i = idx >> 6, f = idx & 63;
    int b = g_obin[i];
    float ui = -g_s[i];
    float e1 = g_e1[i], e2 = g_e2[i];
    float acc = e1 * g_B1[b*64 + f] + e2 * g_B2[b*64 + f];
    int st = g_tStart[b], en = g_tStart[b+1];
    for (int m = st; m < en; m++) {
        int j = g_tOrder[m];
        float tj = g_t[j];
        float hv = g_h[j*64 + f];
        acc += (tj > ui) ? e1 * g_w1[j] * hv : e2 * g_w2[j] * hv;
    }
    out[idx] = acc > 0.f ? acc : expm1f(acc);
}

// ---------------- launch ----------------
extern "C" void kernel_launch(void* const* d_in, const int* in_sizes, int n_in,
                              void* d_out, int out_size) {
    const float* x      = (const float*)d_in[0];
    // d_in[1] = adj (all-ones bool mask; no effect on the math)
    const float* intent = (const float*)d_in[2];
    const float* W      = (const float*)d_in[3];
    const float* a      = (const float*)d_in[4];
    float* out = (float*)d_out;

    k_gemm <<<256,  256>>>(x, W, intent, a);
    k_count<<<NN/256, 256>>>();
    k_hub  <<<1,   1024>>>();
    k_wacc <<<NN/8, 256>>>();
    k_gscan<<<FF,  1024>>>();
    k_out  <<<(NN*FF)/256, 256>>>(out);
}